// round 1
// baseline (speedup 1.0000x reference)
#include <cuda_runtime.h>
#include <cstdint>
#include <cstddef>

// Problem constants (fixed shapes)
#define BB 8
#define LQ 10000
#define LIN 10000
#define CC 256
#define NH 8
#define NP 4
#define HD 32
#define DFF 1024
#define HIMG 100
#define WIMG 100
#define NROWS (BB * LQ)   // 80000

// ---------------------------------------------------------------------------
// Scratch (device globals; no allocations allowed)
// ---------------------------------------------------------------------------
__device__ float g_value  [NROWS * CC];     // [B,Lin,NH,HD]
__device__ float g_off    [NROWS * NH * NP * 2];
__device__ float g_awl    [NROWS * NH * NP];
__device__ float g_attn   [NROWS * CC];
__device__ float g_attnout[NROWS * CC];
__device__ float g_q      [NROWS * CC];
__device__ float g_hidden [NROWS * DFF];
__device__ float g_ffnout [NROWS * CC];

// ---------------------------------------------------------------------------
// Generic register-tiled SGEMM:  C[M,N] = A[M,K] @ B[K,N] + bias (optional relu)
// Requires M%BM==0, N%BN==0, K%BK==0, K%4==0, N%4==0, 256 threads.
// ---------------------------------------------------------------------------
template <int BM, int BN, int BK, int TM, int TN, bool RELU>
__global__ void __launch_bounds__(256)
sgemm_kernel(int M, int N, int K,
             const float* __restrict__ A,
             const float* __restrict__ B,
             const float* __restrict__ bias,
             float* __restrict__ C)
{
    static_assert((BM / TM) * (BN / TN) == 256, "need 256 threads");
    static_assert(BK % 4 == 0 && BN % 4 == 0, "vec loads");

    __shared__ float As[BK][BM];
    __shared__ float Bs[BK][BN];

    const int tid  = threadIdx.x;
    const int cRow = blockIdx.y;
    const int cCol = blockIdx.x;

    const float* Ap = A + (size_t)cRow * BM * K;
    const float* Bp = B + (size_t)cCol * BN;
    float*       Cp = C + (size_t)cRow * BM * N + (size_t)cCol * BN;
    const float* biasp = bias + (size_t)cCol * BN;

    // A-tile loader mapping (float4 along K, transposed into As)
    const int aRow = tid / (BK / 4);
    const int aCol = (tid % (BK / 4)) * 4;
    constexpr int aStride = 256 / (BK / 4);
    // B-tile loader mapping (float4 along N)
    const int bRow = tid / (BN / 4);
    const int bCol = (tid % (BN / 4)) * 4;
    constexpr int bStride = 256 / (BN / 4);

    const int tCol = tid % (BN / TN);
    const int tRow = tid / (BN / TN);

    float acc[TM][TN];
#pragma unroll
    for (int i = 0; i < TM; i++)
#pragma unroll
        for (int j = 0; j < TN; j++) acc[i][j] = 0.0f;

    float rM[TM], rN[TN];

    for (int k0 = 0; k0 < K; k0 += BK) {
#pragma unroll
        for (int r = aRow; r < BM; r += aStride) {
            float4 v = *reinterpret_cast<const float4*>(&Ap[(size_t)r * K + k0 + aCol]);
            As[aCol + 0][r] = v.x;
            As[aCol + 1][r] = v.y;
            As[aCol + 2][r] = v.z;
            As[aCol + 3][r] = v.w;
        }
#pragma unroll
        for (int r = bRow; r < BK; r += bStride) {
            *reinterpret_cast<float4*>(&Bs[r][bCol]) =
                *reinterpret_cast<const float4*>(&Bp[(size_t)(k0 + r) * N + bCol]);
        }
        __syncthreads();

#pragma unroll
        for (int k = 0; k < BK; k++) {
#pragma unroll
            for (int i = 0; i < TM; i++) rM[i] = As[k][tRow * TM + i];
#pragma unroll
            for (int j = 0; j < TN; j++) rN[j] = Bs[k][tCol * TN + j];
#pragma unroll
            for (int i = 0; i < TM; i++)
#pragma unroll
                for (int j = 0; j < TN; j++)
                    acc[i][j] = fmaf(rM[i], rN[j], acc[i][j]);
        }
        __syncthreads();
    }

#pragma unroll
    for (int i = 0; i < TM; i++) {
#pragma unroll
        for (int j = 0; j < TN; j++) {
            float v = acc[i][j] + biasp[tCol * TN + j];
            if (RELU) v = fmaxf(v, 0.0f);
            Cp[(size_t)(tRow * TM + i) * N + tCol * TN + j] = v;
        }
    }
}

// ---------------------------------------------------------------------------
// Deformable sampling + attention aggregation.
// One warp per (b, q, h); lane = head-dim element.
// attn[b,q,h*HD+d] = sum_p softmax(awl)[p] * bilinear(value[b,:,h,d], loc[p])
// ---------------------------------------------------------------------------
__global__ void __launch_bounds__(256)
sample_kernel(const float* __restrict__ value,   // [B,Lin,NH,HD]
              const float* __restrict__ off,     // [B,Lq,NH,NP,2]
              const float* __restrict__ awl,     // [B,Lq,NH,NP] logits
              const float* __restrict__ ref,     // [B,Lq,1,2]
              float* __restrict__ attn)          // [B,Lq,C]
{
    const int warp = (blockIdx.x * blockDim.x + threadIdx.x) >> 5;
    const int lane = threadIdx.x & 31;
    if (warp >= BB * LQ * NH) return;

    const int h  = warp % NH;
    const int bq = warp / NH;          // b*Lq + q
    const int b  = bq / LQ;

    // softmax over NP=4 logits (uniform across warp; cached loads)
    const float* lg = awl + (size_t)bq * (NH * NP) + h * NP;
    float l0 = lg[0], l1 = lg[1], l2 = lg[2], l3 = lg[3];
    float m  = fmaxf(fmaxf(l0, l1), fmaxf(l2, l3));
    float e0 = expf(l0 - m), e1 = expf(l1 - m), e2 = expf(l2 - m), e3 = expf(l3 - m);
    float inv = 1.0f / (e0 + e1 + e2 + e3);
    float w[NP] = {e0 * inv, e1 * inv, e2 * inv, e3 * inv};

    const float rx = ref[(size_t)bq * 2 + 0];
    const float ry = ref[(size_t)bq * 2 + 1];

    const float* ofp = off + ((size_t)bq * NH + h) * (NP * 2);
    const float* vb  = value + ((size_t)b * LIN) * CC + h * HD + lane;

    float acc = 0.0f;

#pragma unroll
    for (int p = 0; p < NP; p++) {
        const float ox = ofp[p * 2 + 0];
        const float oy = ofp[p * 2 + 1];
        // loc = ref + off/[W,H]; pixel coord = loc*[W,H] - 0.5
        const float x = fmaf(rx, (float)WIMG, ox) - 0.5f;
        const float y = fmaf(ry, (float)HIMG, oy) - 0.5f;
        const float xf = floorf(x), yf = floorf(y);
        const float lx = x - xf, ly = y - yf;
        const int x0 = (int)xf, y0 = (int)yf;
        const float wp = w[p];

        const float w00 = (1.0f - lx) * (1.0f - ly) * wp;
        const float w10 = lx * (1.0f - ly) * wp;
        const float w01 = (1.0f - lx) * ly * wp;
        const float w11 = lx * ly * wp;

        if (x0 >= 0 && x0 < WIMG && y0 >= 0 && y0 < HIMG)
            acc = fmaf(w00, __ldg(vb + (size_t)(y0 * WIMG + x0) * CC), acc);
        if (x0 + 1 >= 0 && x0 + 1 < WIMG && y0 >= 0 && y0 < HIMG)
            acc = fmaf(w10, __ldg(vb + (size_t)(y0 * WIMG + x0 + 1) * CC), acc);
        if (x0 >= 0 && x0 < WIMG && y0 + 1 >= 0 && y0 + 1 < HIMG)
            acc = fmaf(w01, __ldg(vb + (size_t)((y0 + 1) * WIMG + x0) * CC), acc);
        if (x0 + 1 >= 0 && x0 + 1 < WIMG && y0 + 1 >= 0 && y0 + 1 < HIMG)
            acc = fmaf(w11, __ldg(vb + (size_t)((y0 + 1) * WIMG + x0 + 1) * CC), acc);
    }

    attn[(size_t)bq * CC + h * HD + lane] = acc;
}

// ---------------------------------------------------------------------------
// out[row] = LayerNorm(x[row] + res[row]) * g + be    (one warp per row, C=256)
// ---------------------------------------------------------------------------
__global__ void __launch_bounds__(256)
add_ln_kernel(const float* __restrict__ x,
              const float* __restrict__ res,
              const float* __restrict__ g,
              const float* __restrict__ be,
              float* __restrict__ out)
{
    const int row  = (blockIdx.x * blockDim.x + threadIdx.x) >> 5;
    const int lane = threadIdx.x & 31;
    if (row >= NROWS) return;

    const float* xr = x   + (size_t)row * CC;
    const float* rr = res + (size_t)row * CC;

    float v[CC / 32];
    float s = 0.0f;
#pragma unroll
    for (int j = 0; j < CC / 32; j++) {
        const int c = lane + 32 * j;
        v[j] = xr[c] + rr[c];
        s += v[j];
    }
#pragma unroll
    for (int o = 16; o > 0; o >>= 1) s += __shfl_xor_sync(0xFFFFFFFFu, s, o);
    const float mean = s * (1.0f / CC);

    float vs = 0.0f;
#pragma unroll
    for (int j = 0; j < CC / 32; j++) {
        const float d = v[j] - mean;
        vs += d * d;
    }
#pragma unroll
    for (int o = 16; o > 0; o >>= 1) vs += __shfl_xor_sync(0xFFFFFFFFu, vs, o);
    const float rstd = rsqrtf(vs * (1.0f / CC) + 1e-5f);

    float* orow = out + (size_t)row * CC;
#pragma unroll
    for (int j = 0; j < CC / 32; j++) {
        const int c = lane + 32 * j;
        orow[c] = (v[j] - mean) * rstd * g[c] + be[c];
    }
}

// ---------------------------------------------------------------------------
// Launch
// ---------------------------------------------------------------------------
extern "C" void kernel_launch(void* const* d_in, const int* in_sizes, int n_in,
                              void* d_out, int out_size)
{
    const float* query = (const float*)d_in[0];
    const float* src   = (const float*)d_in[1];
    const float* ref   = (const float*)d_in[2];
    // d_in[3]=spatial_shapes(int64), d_in[4]=level_start_index(int64): fixed 100x100, start 0
    const float* W_off = (const float*)d_in[5];
    const float* b_off = (const float*)d_in[6];
    const float* W_aw  = (const float*)d_in[7];
    const float* b_aw  = (const float*)d_in[8];
    const float* W_val = (const float*)d_in[9];
    const float* b_val = (const float*)d_in[10];
    const float* W_out = (const float*)d_in[11];
    const float* b_out = (const float*)d_in[12];
    const float* g1    = (const float*)d_in[13];
    const float* be1   = (const float*)d_in[14];
    const float* W1    = (const float*)d_in[15];
    const float* b1    = (const float*)d_in[16];
    const float* W2    = (const float*)d_in[17];
    const float* b2    = (const float*)d_in[18];
    const float* g2    = (const float*)d_in[19];
    const float* be2   = (const float*)d_in[20];
    float* out = (float*)d_out;

    float *p_value, *p_off, *p_awl, *p_attn, *p_attnout, *p_q, *p_hidden, *p_ffnout;
    cudaGetSymbolAddress((void**)&p_value,   g_value);
    cudaGetSymbolAddress((void**)&p_off,     g_off);
    cudaGetSymbolAddress((void**)&p_awl,     g_awl);
    cudaGetSymbolAddress((void**)&p_attn,    g_attn);
    cudaGetSymbolAddress((void**)&p_attnout, g_attnout);
    cudaGetSymbolAddress((void**)&p_q,       g_q);
    cudaGetSymbolAddress((void**)&p_hidden,  g_hidden);
    cudaGetSymbolAddress((void**)&p_ffnout,  g_ffnout);

    // 1) value = src @ W_val + b_val                      [80000,256]
    {
        dim3 grid(CC / 128, NROWS / 128);
        sgemm_kernel<128, 128, 8, 8, 8, false><<<grid, 256>>>(
            NROWS, CC, CC, src, W_val, b_val, p_value);
    }
    // 2) off = query @ W_off + b_off                      [80000,64]
    {
        dim3 grid(64 / 64, NROWS / 128);
        sgemm_kernel<128, 64, 8, 8, 4, false><<<grid, 256>>>(
            NROWS, 64, CC, query, W_off, b_off, p_off);
    }
    // 3) aw logits = query @ W_aw + b_aw                  [80000,32]
    {
        dim3 grid(32 / 32, NROWS / 128);
        sgemm_kernel<128, 32, 8, 8, 2, false><<<grid, 256>>>(
            NROWS, 32, CC, query, W_aw, b_aw, p_awl);
    }
    // 4) deformable sampling + aggregation -> attn        [80000,256]
    {
        const int warps = BB * LQ * NH;                    // 640000
        sample_kernel<<<(warps + 7) / 8, 256>>>(p_value, p_off, p_awl, ref, p_attn);
    }
    // 5) attnout = attn @ W_out + b_out
    {
        dim3 grid(CC / 128, NROWS / 128);
        sgemm_kernel<128, 128, 8, 8, 8, false><<<grid, 256>>>(
            NROWS, CC, CC, p_attn, W_out, b_out, p_attnout);
    }
    // 6) q = LN(query + attnout)
    add_ln_kernel<<<NROWS / 8, 256>>>(p_attnout, query, g1, be1, p_q);
    // 7) hidden = relu(q @ W1 + b1)                       [80000,1024]
    {
        dim3 grid(DFF / 128, NROWS / 128);
        sgemm_kernel<128, 128, 8, 8, 8, true><<<grid, 256>>>(
            NROWS, DFF, CC, p_q, W1, b1, p_hidden);
    }
    // 8) ffnout = hidden @ W2 + b2                        [80000,256]
    {
        dim3 grid(CC / 128, NROWS / 128);
        sgemm_kernel<128, 128, 8, 8, 8, false><<<grid, 256>>>(
            NROWS, CC, DFF, p_hidden, W2, b2, p_ffnout);
    }
    // 9) out = LN(q + ffnout)
    add_ln_kernel<<<NROWS / 8, 256>>>(p_ffnout, p_q, g2, be2, out);
}

// round 4
// speedup vs baseline: 2.2806x; 2.2806x over previous
#include <cuda_runtime.h>
#include <cstdint>
#include <cstddef>

// Problem constants (fixed shapes)
#define BB 8
#define LQ 10000
#define LIN 10000
#define CC 256
#define NH 8
#define NP 4
#define HD 32
#define DFF 1024
#define HIMG 100
#define WIMG 100
#define NROWS (BB * LQ)   // 80000

// ---------------------------------------------------------------------------
// Scratch (device globals; no allocations allowed)
// ---------------------------------------------------------------------------
__device__ float g_value  [NROWS * CC];     // [B,Lin,NH,HD]
__device__ float g_off    [NROWS * NH * NP * 2];
__device__ float g_awl    [NROWS * NH * NP];
__device__ float g_attn   [NROWS * CC];
__device__ float g_attnout[NROWS * CC];
__device__ float g_q      [NROWS * CC];
__device__ float g_hidden [NROWS * DFF];
__device__ float g_ffnout [NROWS * CC];

// ---------------------------------------------------------------------------
// TF32 helpers
// ---------------------------------------------------------------------------
__device__ __forceinline__ float f2tf32(float x) {
    uint32_t u;
    asm("cvt.rna.tf32.f32 %0, %1;" : "=r"(u) : "f"(x));
    return __uint_as_float(u);
}

__device__ __forceinline__ void mma_tf32(float* d, const uint32_t* a, const uint32_t* b) {
    asm volatile(
        "mma.sync.aligned.m16n8k8.row.col.f32.tf32.tf32.f32 "
        "{%0,%1,%2,%3}, {%4,%5,%6,%7}, {%8,%9}, {%0,%1,%2,%3};"
        : "+f"(d[0]), "+f"(d[1]), "+f"(d[2]), "+f"(d[3])
        : "r"(a[0]), "r"(a[1]), "r"(a[2]), "r"(a[3]),
          "r"(b[0]), "r"(b[1]));
}

// ---------------------------------------------------------------------------
// TF32 tensor-core GEMM: C[M,N] = A[M,K] @ B[K,N] + bias (optional relu)
// BM=128, BN=128, BK=32, 256 threads (8 warps, 2x4 warp grid, 64x32 warp tile)
// Requires M%128==0, N%128==0, K%32==0.
// ---------------------------------------------------------------------------
#define TGM 128
#define TGN 128
#define TGK 32
#define LDA 36    // TGK + 4
#define LDB 136   // TGN + 8

template <bool RELU>
__global__ void __launch_bounds__(256)
tf32_gemm_kernel(int M, int N, int K,
                 const float* __restrict__ A,
                 const float* __restrict__ B,
                 const float* __restrict__ bias,
                 float* __restrict__ C)
{
    __shared__ float As[TGM * LDA];
    __shared__ float Bs[TGK * LDB];

    const int tid  = threadIdx.x;
    const int lane = tid & 31;
    const int warp = tid >> 5;
    const int g    = lane >> 2;   // groupID 0..7
    const int t    = lane & 3;    // thread-in-group 0..3

    const int wr = warp >> 2;     // 0..1
    const int wc = warp & 3;      // 0..3
    const int wm0 = wr * 64;
    const int wn0 = wc * 32;

    const int blockM = blockIdx.y * TGM;
    const int blockN = blockIdx.x * TGN;

    const float* Ap = A + (size_t)blockM * K;
    const float* Bp = B + blockN;
    const float* biasp = bias + blockN;

    // Global-load mappings (float4)
    const int ar = tid >> 3;            // 0..31 ; rows ar + 32*i
    const int ac = (tid & 7) * 4;       // k col
    const int br = tid >> 5;            // 0..7  ; rows br + 8*i
    const int bc = (tid & 31) * 4;      // n col

    float4 pfA[4], pfB[4];

    float acc[4][4][4];
#pragma unroll
    for (int i = 0; i < 4; i++)
#pragma unroll
        for (int j = 0; j < 4; j++)
#pragma unroll
            for (int r = 0; r < 4; r++) acc[i][j][r] = 0.0f;

    const int ntiles = K / TGK;

    // --- load tile 0 ---
#pragma unroll
    for (int i = 0; i < 4; i++)
        pfA[i] = *reinterpret_cast<const float4*>(&Ap[(size_t)(ar + 32 * i) * K + ac]);
#pragma unroll
    for (int i = 0; i < 4; i++)
        pfB[i] = *reinterpret_cast<const float4*>(&Bp[(size_t)(br + 8 * i) * N + bc]);

#pragma unroll
    for (int i = 0; i < 4; i++) {
        float* d = &As[(ar + 32 * i) * LDA + ac];
        d[0] = f2tf32(pfA[i].x); d[1] = f2tf32(pfA[i].y);
        d[2] = f2tf32(pfA[i].z); d[3] = f2tf32(pfA[i].w);
    }
#pragma unroll
    for (int i = 0; i < 4; i++) {
        float* d = &Bs[(br + 8 * i) * LDB + bc];
        d[0] = f2tf32(pfB[i].x); d[1] = f2tf32(pfB[i].y);
        d[2] = f2tf32(pfB[i].z); d[3] = f2tf32(pfB[i].w);
    }
    __syncthreads();

    for (int tIdx = 0; tIdx < ntiles; tIdx++) {
        if (tIdx + 1 < ntiles) {
            const int k0 = (tIdx + 1) * TGK;
#pragma unroll
            for (int i = 0; i < 4; i++)
                pfA[i] = *reinterpret_cast<const float4*>(&Ap[(size_t)(ar + 32 * i) * K + k0 + ac]);
#pragma unroll
            for (int i = 0; i < 4; i++)
                pfB[i] = *reinterpret_cast<const float4*>(&Bp[(size_t)(k0 + br + 8 * i) * N + bc]);
        }

#pragma unroll
        for (int kk = 0; kk < TGK; kk += 8) {
            uint32_t afr[4][4];
            uint32_t bfr[4][2];
#pragma unroll
            for (int mi = 0; mi < 4; mi++) {
                const int m = wm0 + mi * 16;
                afr[mi][0] = __float_as_uint(As[(m + g)     * LDA + kk + t]);
                afr[mi][1] = __float_as_uint(As[(m + g + 8) * LDA + kk + t]);
                afr[mi][2] = __float_as_uint(As[(m + g)     * LDA + kk + t + 4]);
                afr[mi][3] = __float_as_uint(As[(m + g + 8) * LDA + kk + t + 4]);
            }
#pragma unroll
            for (int ni = 0; ni < 4; ni++) {
                const int n = wn0 + ni * 8;
                bfr[ni][0] = __float_as_uint(Bs[(kk + t)     * LDB + n + g]);
                bfr[ni][1] = __float_as_uint(Bs[(kk + t + 4) * LDB + n + g]);
            }
#pragma unroll
            for (int mi = 0; mi < 4; mi++)
#pragma unroll
                for (int ni = 0; ni < 4; ni++)
                    mma_tf32(acc[mi][ni], afr[mi], bfr[ni]);
        }
        __syncthreads();

        if (tIdx + 1 < ntiles) {
#pragma unroll
            for (int i = 0; i < 4; i++) {
                float* d = &As[(ar + 32 * i) * LDA + ac];
                d[0] = f2tf32(pfA[i].x); d[1] = f2tf32(pfA[i].y);
                d[2] = f2tf32(pfA[i].z); d[3] = f2tf32(pfA[i].w);
            }
#pragma unroll
            for (int i = 0; i < 4; i++) {
                float* d = &Bs[(br + 8 * i) * LDB + bc];
                d[0] = f2tf32(pfB[i].x); d[1] = f2tf32(pfB[i].y);
                d[2] = f2tf32(pfB[i].z); d[3] = f2tf32(pfB[i].w);
            }
            __syncthreads();
        }
    }

    // epilogue: D layout c0:(g,2t) c1:(g,2t+1) c2:(g+8,2t) c3:(g+8,2t+1)
#pragma unroll
    for (int mi = 0; mi < 4; mi++) {
#pragma unroll
        for (int ni = 0; ni < 4; ni++) {
            const int row0 = blockM + wm0 + mi * 16 + g;
            const int col  = blockN + wn0 + ni * 8 + 2 * t;
            const float bx = biasp[wn0 + ni * 8 + 2 * t];
            const float by = biasp[wn0 + ni * 8 + 2 * t + 1];
            float v0 = acc[mi][ni][0] + bx;
            float v1 = acc[mi][ni][1] + by;
            float v2 = acc[mi][ni][2] + bx;
            float v3 = acc[mi][ni][3] + by;
            if (RELU) {
                v0 = fmaxf(v0, 0.0f); v1 = fmaxf(v1, 0.0f);
                v2 = fmaxf(v2, 0.0f); v3 = fmaxf(v3, 0.0f);
            }
            *reinterpret_cast<float2*>(&C[(size_t)row0 * N + col])       = make_float2(v0, v1);
            *reinterpret_cast<float2*>(&C[(size_t)(row0 + 8) * N + col]) = make_float2(v2, v3);
        }
    }
}

// ---------------------------------------------------------------------------
// FFMA register-tiled SGEMM (kept for small-N projections)
// ---------------------------------------------------------------------------
template <int BM, int BN, int BK, int TM, int TN, bool RELU>
__global__ void __launch_bounds__(256)
sgemm_kernel(int M, int N, int K,
             const float* __restrict__ A,
             const float* __restrict__ B,
             const float* __restrict__ bias,
             float* __restrict__ C)
{
    static_assert((BM / TM) * (BN / TN) == 256, "need 256 threads");

    __shared__ float As[BK][BM];
    __shared__ float Bs[BK][BN];

    const int tid  = threadIdx.x;
    const int cRow = blockIdx.y;
    const int cCol = blockIdx.x;

    const float* Ap = A + (size_t)cRow * BM * K;
    const float* Bp = B + (size_t)cCol * BN;
    float*       Cp = C + (size_t)cRow * BM * N + (size_t)cCol * BN;
    const float* biasp = bias + (size_t)cCol * BN;

    const int aRow = tid / (BK / 4);
    const int aCol = (tid % (BK / 4)) * 4;
    constexpr int aStride = 256 / (BK / 4);
    const int bRow = tid / (BN / 4);
    const int bCol = (tid % (BN / 4)) * 4;
    constexpr int bStride = 256 / (BN / 4);

    const int tCol = tid % (BN / TN);
    const int tRow = tid / (BN / TN);

    float acc[TM][TN];
#pragma unroll
    for (int i = 0; i < TM; i++)
#pragma unroll
        for (int j = 0; j < TN; j++) acc[i][j] = 0.0f;

    float rM[TM], rN[TN];

    for (int k0 = 0; k0 < K; k0 += BK) {
#pragma unroll
        for (int r = aRow; r < BM; r += aStride) {
            float4 v = *reinterpret_cast<const float4*>(&Ap[(size_t)r * K + k0 + aCol]);
            As[aCol + 0][r] = v.x;
            As[aCol + 1][r] = v.y;
            As[aCol + 2][r] = v.z;
            As[aCol + 3][r] = v.w;
        }
#pragma unroll
        for (int r = bRow; r < BK; r += bStride) {
            *reinterpret_cast<float4*>(&Bs[r][bCol]) =
                *reinterpret_cast<const float4*>(&Bp[(size_t)(k0 + r) * N + bCol]);
        }
        __syncthreads();

#pragma unroll
        for (int k = 0; k < BK; k++) {
#pragma unroll
            for (int i = 0; i < TM; i++) rM[i] = As[k][tRow * TM + i];
#pragma unroll
            for (int j = 0; j < TN; j++) rN[j] = Bs[k][tCol * TN + j];
#pragma unroll
            for (int i = 0; i < TM; i++)
#pragma unroll
                for (int j = 0; j < TN; j++)
                    acc[i][j] = fmaf(rM[i], rN[j], acc[i][j]);
        }
        __syncthreads();
    }

#pragma unroll
    for (int i = 0; i < TM; i++) {
#pragma unroll
        for (int j = 0; j < TN; j++) {
            float v = acc[i][j] + biasp[tCol * TN + j];
            if (RELU) v = fmaxf(v, 0.0f);
            Cp[(size_t)(tRow * TM + i) * N + tCol * TN + j] = v;
        }
    }
}

// ---------------------------------------------------------------------------
// Deformable sampling + attention aggregation (warp per (b,q,h))
// ---------------------------------------------------------------------------
__global__ void __launch_bounds__(256)
sample_kernel(const float* __restrict__ value,
              const float* __restrict__ off,
              const float* __restrict__ awl,
              const float* __restrict__ ref,
              float* __restrict__ attn)
{
    const int warp = (blockIdx.x * blockDim.x + threadIdx.x) >> 5;
    const int lane = threadIdx.x & 31;
    if (warp >= BB * LQ * NH) return;

    const int h  = warp % NH;
    const int bq = warp / NH;
    const int b  = bq / LQ;

    const float* lg = awl + (size_t)bq * (NH * NP) + h * NP;
    float l0 = lg[0], l1 = lg[1], l2 = lg[2], l3 = lg[3];
    float m  = fmaxf(fmaxf(l0, l1), fmaxf(l2, l3));
    float e0 = expf(l0 - m), e1 = expf(l1 - m), e2 = expf(l2 - m), e3 = expf(l3 - m);
    float inv = 1.0f / (e0 + e1 + e2 + e3);
    float w[NP] = {e0 * inv, e1 * inv, e2 * inv, e3 * inv};

    const float rx = ref[(size_t)bq * 2 + 0];
    const float ry = ref[(size_t)bq * 2 + 1];

    const float* ofp = off + ((size_t)bq * NH + h) * (NP * 2);
    const float* vb  = value + ((size_t)b * LIN) * CC + h * HD + lane;

    float acc = 0.0f;

#pragma unroll
    for (int p = 0; p < NP; p++) {
        const float ox = ofp[p * 2 + 0];
        const float oy = ofp[p * 2 + 1];
        const float x = fmaf(rx, (float)WIMG, ox) - 0.5f;
        const float y = fmaf(ry, (float)HIMG, oy) - 0.5f;
        const float xf = floorf(x), yf = floorf(y);
        const float lx = x - xf, ly = y - yf;
        const int x0 = (int)xf, y0 = (int)yf;
        const float wp = w[p];

        const float w00 = (1.0f - lx) * (1.0f - ly) * wp;
        const float w10 = lx * (1.0f - ly) * wp;
        const float w01 = (1.0f - lx) * ly * wp;
        const float w11 = lx * ly * wp;

        if (x0 >= 0 && x0 < WIMG && y0 >= 0 && y0 < HIMG)
            acc = fmaf(w00, __ldg(vb + (size_t)(y0 * WIMG + x0) * CC), acc);
        if (x0 + 1 >= 0 && x0 + 1 < WIMG && y0 >= 0 && y0 < HIMG)
            acc = fmaf(w10, __ldg(vb + (size_t)(y0 * WIMG + x0 + 1) * CC), acc);
        if (x0 >= 0 && x0 < WIMG && y0 + 1 >= 0 && y0 + 1 < HIMG)
            acc = fmaf(w01, __ldg(vb + (size_t)((y0 + 1) * WIMG + x0) * CC), acc);
        if (x0 + 1 >= 0 && x0 + 1 < WIMG && y0 + 1 >= 0 && y0 + 1 < HIMG)
            acc = fmaf(w11, __ldg(vb + (size_t)((y0 + 1) * WIMG + x0 + 1) * CC), acc);
    }

    attn[(size_t)bq * CC + h * HD + lane] = acc;
}

// ---------------------------------------------------------------------------
// out[row] = LayerNorm(x[row] + res[row]) * g + be (warp per row)
// ---------------------------------------------------------------------------
__global__ void __launch_bounds__(256)
add_ln_kernel(const float* __restrict__ x,
              const float* __restrict__ res,
              const float* __restrict__ g,
              const float* __restrict__ be,
              float* __restrict__ out)
{
    const int row  = (blockIdx.x * blockDim.x + threadIdx.x) >> 5;
    const int lane = threadIdx.x & 31;
    if (row >= NROWS) return;

    const float* xr = x   + (size_t)row * CC;
    const float* rr = res + (size_t)row * CC;

    float v[CC / 32];
    float s = 0.0f;
#pragma unroll
    for (int j = 0; j < CC / 32; j++) {
        const int c = lane + 32 * j;
        v[j] = xr[c] + rr[c];
        s += v[j];
    }
#pragma unroll
    for (int o = 16; o > 0; o >>= 1) s += __shfl_xor_sync(0xFFFFFFFFu, s, o);
    const float mean = s * (1.0f / CC);

    float vs = 0.0f;
#pragma unroll
    for (int j = 0; j < CC / 32; j++) {
        const float d = v[j] - mean;
        vs += d * d;
    }
#pragma unroll
    for (int o = 16; o > 0; o >>= 1) vs += __shfl_xor_sync(0xFFFFFFFFu, vs, o);
    const float rstd = rsqrtf(vs * (1.0f / CC) + 1e-5f);

    float* orow = out + (size_t)row * CC;
#pragma unroll
    for (int j = 0; j < CC / 32; j++) {
        const int c = lane + 32 * j;
        orow[c] = (v[j] - mean) * rstd * g[c] + be[c];
    }
}

// ---------------------------------------------------------------------------
// Launch
// ---------------------------------------------------------------------------
extern "C" void kernel_launch(void* const* d_in, const int* in_sizes, int n_in,
                              void* d_out, int out_size)
{
    const float* query = (const float*)d_in[0];
    const float* src   = (const float*)d_in[1];
    const float* ref   = (const float*)d_in[2];
    const float* W_off = (const float*)d_in[5];
    const float* b_off = (const float*)d_in[6];
    const float* W_aw  = (const float*)d_in[7];
    const float* b_aw  = (const float*)d_in[8];
    const float* W_val = (const float*)d_in[9];
    const float* b_val = (const float*)d_in[10];
    const float* W_out = (const float*)d_in[11];
    const float* b_out = (const float*)d_in[12];
    const float* g1    = (const float*)d_in[13];
    const float* be1   = (const float*)d_in[14];
    const float* W1    = (const float*)d_in[15];
    const float* b1    = (const float*)d_in[16];
    const float* W2    = (const float*)d_in[17];
    const float* b2    = (const float*)d_in[18];
    const float* g2    = (const float*)d_in[19];
    const float* be2   = (const float*)d_in[20];
    float* out = (float*)d_out;

    float *p_value, *p_off, *p_awl, *p_attn, *p_attnout, *p_q, *p_hidden, *p_ffnout;
    cudaGetSymbolAddress((void**)&p_value,   g_value);
    cudaGetSymbolAddress((void**)&p_off,     g_off);
    cudaGetSymbolAddress((void**)&p_awl,     g_awl);
    cudaGetSymbolAddress((void**)&p_attn,    g_attn);
    cudaGetSymbolAddress((void**)&p_attnout, g_attnout);
    cudaGetSymbolAddress((void**)&p_q,       g_q);
    cudaGetSymbolAddress((void**)&p_hidden,  g_hidden);
    cudaGetSymbolAddress((void**)&p_ffnout,  g_ffnout);

    // 1) value = src @ W_val + b_val     [80000,256] (TF32 TC)
    {
        dim3 grid(CC / TGN, NROWS / TGM);
        tf32_gemm_kernel<false><<<grid, 256>>>(NROWS, CC, CC, src, W_val, b_val, p_value);
    }
    // 2) off = query @ W_off + b_off     [80000,64] (FFMA)
    {
        dim3 grid(1, NROWS / 128);
        sgemm_kernel<128, 64, 8, 8, 4, false><<<grid, 256>>>(
            NROWS, 64, CC, query, W_off, b_off, p_off);
    }
    // 3) aw logits = query @ W_aw + b_aw [80000,32] (FFMA)
    {
        dim3 grid(1, NROWS / 128);
        sgemm_kernel<128, 32, 8, 8, 2, false><<<grid, 256>>>(
            NROWS, 32, CC, query, W_aw, b_aw, p_awl);
    }
    // 4) deformable sampling + aggregation -> attn
    {
        const int warps = BB * LQ * NH;
        sample_kernel<<<(warps + 7) / 8, 256>>>(p_value, p_off, p_awl, ref, p_attn);
    }
    // 5) attnout = attn @ W_out + b_out  (TF32 TC)
    {
        dim3 grid(CC / TGN, NROWS / TGM);
        tf32_gemm_kernel<false><<<grid, 256>>>(NROWS, CC, CC, p_attn, W_out, b_out, p_attnout);
    }
    // 6) q = LN(query + attnout)
    add_ln_kernel<<<NROWS / 8, 256>>>(p_attnout, query, g1, be1, p_q);
    // 7) hidden = relu(q @ W1 + b1)      [80000,1024] (TF32 TC)
    {
        dim3 grid(DFF / TGN, NROWS / TGM);
        tf32_gemm_kernel<true><<<grid, 256>>>(NROWS, DFF, CC, p_q, W1, b1, p_hidden);
    }
    // 8) ffnout = hidden @ W2 + b2       [80000,256] (TF32 TC)
    {
        dim3 grid(CC / TGN, NROWS / TGM);
        tf32_gemm_kernel<false><<<grid, 256>>>(NROWS, CC, DFF, p_hidden, W2, b2, p_ffnout);
    }
    // 9) out = LN(q + ffnout)
    add_ln_kernel<<<NROWS / 8, 256>>>(p_ffnout, p_q, g2, be2, out);
}

// round 6
// speedup vs baseline: 3.1036x; 1.3609x over previous
#include <cuda_runtime.h>
#include <cstdint>
#include <cstddef>

// Problem constants (fixed shapes)
#define BB 8
#define LQ 10000
#define LIN 10000
#define CC 256
#define NH 8
#define NP 4
#define HD 32
#define DFF 1024
#define HIMG 100
#define WIMG 100
#define NROWS (BB * LQ)   // 80000

// ---------------------------------------------------------------------------
// Scratch (device globals; no allocations allowed)
// ---------------------------------------------------------------------------
__device__ float g_value  [NROWS * CC];
__device__ float g_off    [NROWS * NH * NP * 2];
__device__ float g_awl    [NROWS * NH * NP];
__device__ float g_attn   [NROWS * CC];
__device__ float g_attnout[NROWS * CC];
__device__ float g_q      [NROWS * CC];
__device__ float g_hidden [NROWS * DFF];
__device__ float g_ffnout [NROWS * CC];

// ---------------------------------------------------------------------------
// Async-copy helpers
// ---------------------------------------------------------------------------
__device__ __forceinline__ void cp_async16(void* smem_dst, const void* gsrc) {
    uint32_t d = (uint32_t)__cvta_generic_to_shared(smem_dst);
    asm volatile("cp.async.cg.shared.global [%0], [%1], 16;\n" :: "r"(d), "l"(gsrc));
}
__device__ __forceinline__ void cp_commit() {
    asm volatile("cp.async.commit_group;\n");
}
template <int N>
__device__ __forceinline__ void cp_wait() {
    asm volatile("cp.async.wait_group %0;\n" :: "n"(N));
}

__device__ __forceinline__ void mma_tf32(float* d, const uint32_t* a, const uint32_t* b) {
    asm volatile(
        "mma.sync.aligned.m16n8k8.row.col.f32.tf32.tf32.f32 "
        "{%0,%1,%2,%3}, {%4,%5,%6,%7}, {%8,%9}, {%0,%1,%2,%3};"
        : "+f"(d[0]), "+f"(d[1]), "+f"(d[2]), "+f"(d[3])
        : "r"(a[0]), "r"(a[1]), "r"(a[2]), "r"(a[3]),
          "r"(b[0]), "r"(b[1]));
}

// ---------------------------------------------------------------------------
// TF32 tensor-core GEMM with 3-stage cp.async pipeline.
// C[M,N] = A[M,K] @ B[K,N] + bias (optional relu)
// BM=128, BN=128, BK=32, 256 threads (8 warps, 2x4 grid, 64x32 warp tile)
// ---------------------------------------------------------------------------
#define TGM 128
#define TGN 128
#define TGK 32
#define LDA 36    // row stride in floats (144B, 16B-aligned)
#define LDB 136   // row stride in floats (544B, 16B-aligned)
#define STAGES 3
#define A_TILE (TGM * LDA)    // 4608 floats
#define B_TILE (TGK * LDB)    // 4352 floats
#define GEMM_SMEM_BYTES ((size_t)STAGES * (A_TILE + B_TILE) * 4)  // 107520

template <bool RELU>
__global__ void __launch_bounds__(256)
tf32_gemm_kernel(int M, int N, int K,
                 const float* __restrict__ A,
                 const float* __restrict__ B,
                 const float* __restrict__ bias,
                 float* __restrict__ C)
{
    extern __shared__ float sm[];
    float* AsBase = sm;
    float* BsBase = sm + STAGES * A_TILE;

    const int tid  = threadIdx.x;
    const int lane = tid & 31;
    const int warp = tid >> 5;
    const int g    = lane >> 2;   // 0..7
    const int t4   = lane & 3;    // 0..3

    const int wm0 = (warp >> 2) * 64;
    const int wn0 = (warp & 3) * 32;

    const int blockM = blockIdx.y * TGM;
    const int blockN = blockIdx.x * TGN;

    const float* Ap = A + (size_t)blockM * K;
    const float* Bp = B + blockN;
    const float* biasp = bias + blockN;

    // cp.async load mapping (float4 per op, 4 ops each for A and B)
    const int ar = tid >> 3;            // 0..31 ; rows ar + 32*i
    const int ac = (tid & 7) * 4;       // k col
    const int br = tid >> 5;            // 0..7  ; rows br + 8*i
    const int bc = (tid & 31) * 4;      // n col

    float acc[4][4][4];
#pragma unroll
    for (int i = 0; i < 4; i++)
#pragma unroll
        for (int j = 0; j < 4; j++)
#pragma unroll
            for (int r = 0; r < 4; r++) acc[i][j][r] = 0.0f;

    const int ntiles = K / TGK;   // >= 8 for all our shapes

    // prologue: stages 0 and 1
#pragma unroll
    for (int s = 0; s < 2; s++) {
        const int k0 = s * TGK;
        float* as = AsBase + s * A_TILE;
        float* bs = BsBase + s * B_TILE;
#pragma unroll
        for (int i = 0; i < 4; i++)
            cp_async16(&as[(ar + 32 * i) * LDA + ac], &Ap[(size_t)(ar + 32 * i) * K + k0 + ac]);
#pragma unroll
        for (int i = 0; i < 4; i++)
            cp_async16(&bs[(br + 8 * i) * LDB + bc], &Bp[(size_t)(k0 + br + 8 * i) * N + bc]);
        cp_commit();
    }

    int stage = 0;
    for (int kt = 0; kt < ntiles; kt++) {
        if (kt == ntiles - 1) cp_wait<0>(); else cp_wait<1>();
        __syncthreads();

        // issue stage kt+2 (overlaps with compute below)
        if (kt + 2 < ntiles) {
            const int s  = (kt + 2) % STAGES;
            const int k0 = (kt + 2) * TGK;
            float* as = AsBase + s * A_TILE;
            float* bs = BsBase + s * B_TILE;
#pragma unroll
            for (int i = 0; i < 4; i++)
                cp_async16(&as[(ar + 32 * i) * LDA + ac], &Ap[(size_t)(ar + 32 * i) * K + k0 + ac]);
#pragma unroll
            for (int i = 0; i < 4; i++)
                cp_async16(&bs[(br + 8 * i) * LDB + bc], &Bp[(size_t)(k0 + br + 8 * i) * N + bc]);
            cp_commit();
        }

        const float* as = AsBase + stage * A_TILE;
        const float* bs = BsBase + stage * B_TILE;

#pragma unroll
        for (int kk = 0; kk < TGK; kk += 8) {
            uint32_t afr[4][4];
            uint32_t bfr[4][2];
#pragma unroll
            for (int mi = 0; mi < 4; mi++) {
                const int m = wm0 + mi * 16;
                afr[mi][0] = __float_as_uint(as[(m + g)     * LDA + kk + t4]);
                afr[mi][1] = __float_as_uint(as[(m + g + 8) * LDA + kk + t4]);
                afr[mi][2] = __float_as_uint(as[(m + g)     * LDA + kk + t4 + 4]);
                afr[mi][3] = __float_as_uint(as[(m + g + 8) * LDA + kk + t4 + 4]);
            }
#pragma unroll
            for (int ni = 0; ni < 4; ni++) {
                const int n = wn0 + ni * 8;
                bfr[ni][0] = __float_as_uint(bs[(kk + t4)     * LDB + n + g]);
                bfr[ni][1] = __float_as_uint(bs[(kk + t4 + 4) * LDB + n + g]);
            }
#pragma unroll
            for (int mi = 0; mi < 4; mi++)
#pragma unroll
                for (int ni = 0; ni < 4; ni++)
                    mma_tf32(acc[mi][ni], afr[mi], bfr[ni]);
        }
        stage = (stage + 1 == STAGES) ? 0 : stage + 1;
    }

    // epilogue: c0:(g,2t) c1:(g,2t+1) c2:(g+8,2t) c3:(g+8,2t+1)
#pragma unroll
    for (int mi = 0; mi < 4; mi++) {
#pragma unroll
        for (int ni = 0; ni < 4; ni++) {
            const int row0 = blockM + wm0 + mi * 16 + g;
            const int col  = blockN + wn0 + ni * 8 + 2 * t4;
            const float bx = biasp[wn0 + ni * 8 + 2 * t4];
            const float by = biasp[wn0 + ni * 8 + 2 * t4 + 1];
            float v0 = acc[mi][ni][0] + bx;
            float v1 = acc[mi][ni][1] + by;
            float v2 = acc[mi][ni][2] + bx;
            float v3 = acc[mi][ni][3] + by;
            if (RELU) {
                v0 = fmaxf(v0, 0.0f); v1 = fmaxf(v1, 0.0f);
                v2 = fmaxf(v2, 0.0f); v3 = fmaxf(v3, 0.0f);
            }
            *reinterpret_cast<float2*>(&C[(size_t)row0 * N + col])       = make_float2(v0, v1);
            *reinterpret_cast<float2*>(&C[(size_t)(row0 + 8) * N + col]) = make_float2(v2, v3);
        }
    }
}

// ---------------------------------------------------------------------------
// FFMA register-tiled SGEMM (small-N projections)
// ---------------------------------------------------------------------------
template <int BM, int BN, int BK, int TM, int TN, bool RELU>
__global__ void __launch_bounds__(256)
sgemm_kernel(int M, int N, int K,
             const float* __restrict__ A,
             const float* __restrict__ B,
             const float* __restrict__ bias,
             float* __restrict__ C)
{
    static_assert((BM / TM) * (BN / TN) == 256, "need 256 threads");

    __shared__ float As[BK][BM];
    __shared__ float Bs[BK][BN];

    const int tid  = threadIdx.x;
    const float* Ap = A + (size_t)blockIdx.y * BM * K;
    const float* Bp = B + (size_t)blockIdx.x * BN;
    float*       Cp = C + (size_t)blockIdx.y * BM * N + (size_t)blockIdx.x * BN;
    const float* biasp = bias + (size_t)blockIdx.x * BN;

    const int aRow = tid / (BK / 4);
    const int aCol = (tid % (BK / 4)) * 4;
    constexpr int aStride = 256 / (BK / 4);
    const int bRow = tid / (BN / 4);
    const int bCol = (tid % (BN / 4)) * 4;
    constexpr int bStride = 256 / (BN / 4);

    const int tCol = tid % (BN / TN);
    const int tRow = tid / (BN / TN);

    float acc[TM][TN];
#pragma unroll
    for (int i = 0; i < TM; i++)
#pragma unroll
        for (int j = 0; j < TN; j++) acc[i][j] = 0.0f;

    float rM[TM], rN[TN];

    for (int k0 = 0; k0 < K; k0 += BK) {
#pragma unroll
        for (int r = aRow; r < BM; r += aStride) {
            float4 v = *reinterpret_cast<const float4*>(&Ap[(size_t)r * K + k0 + aCol]);
            As[aCol + 0][r] = v.x;
            As[aCol + 1][r] = v.y;
            As[aCol + 2][r] = v.z;
            As[aCol + 3][r] = v.w;
        }
#pragma unroll
        for (int r = bRow; r < BK; r += bStride) {
            *reinterpret_cast<float4*>(&Bs[r][bCol]) =
                *reinterpret_cast<const float4*>(&Bp[(size_t)(k0 + r) * N + bCol]);
        }
        __syncthreads();

#pragma unroll
        for (int k = 0; k < BK; k++) {
#pragma unroll
            for (int i = 0; i < TM; i++) rM[i] = As[k][tRow * TM + i];
#pragma unroll
            for (int j = 0; j < TN; j++) rN[j] = Bs[k][tCol * TN + j];
#pragma unroll
            for (int i = 0; i < TM; i++)
#pragma unroll
                for (int j = 0; j < TN; j++)
                    acc[i][j] = fmaf(rM[i], rN[j], acc[i][j]);
        }
        __syncthreads();
    }

#pragma unroll
    for (int i = 0; i < TM; i++) {
#pragma unroll
        for (int j = 0; j < TN; j++) {
            float v = acc[i][j] + biasp[tCol * TN + j];
            if (RELU) v = fmaxf(v, 0.0f);
            Cp[(size_t)(tRow * TM + i) * N + tCol * TN + j] = v;
        }
    }
}

// ---------------------------------------------------------------------------
// Deformable sampling + attention aggregation.
// One warp per (b,q); lane = (head h = lane>>2, quarter sub = lane&3).
// Each lane accumulates 8 consecutive head-dim channels via 2x float4.
// ---------------------------------------------------------------------------
__global__ void __launch_bounds__(256)
sample_kernel(const float* __restrict__ value,   // [B,Lin,NH,HD]
              const float* __restrict__ off,     // [B,Lq,NH,NP,2]
              const float* __restrict__ awl,     // [B,Lq,NH,NP] logits
              const float* __restrict__ ref,     // [B,Lq,1,2]
              float* __restrict__ attn)          // [B,Lq,C]
{
    const int warp = (blockIdx.x * blockDim.x + threadIdx.x) >> 5;
    const int lane = threadIdx.x & 31;
    if (warp >= BB * LQ) return;

    const int bq  = warp;
    const int b   = bq / LQ;
    const int h   = lane >> 2;
    const int sub = lane & 3;

    // softmax over NP=4 logits for this head (4 lanes duplicate; L1 broadcast)
    const float* lg = awl + (size_t)bq * (NH * NP) + h * NP;
    const float l0 = lg[0], l1 = lg[1], l2 = lg[2], l3 = lg[3];
    const float m  = fmaxf(fmaxf(l0, l1), fmaxf(l2, l3));
    const float e0 = expf(l0 - m), e1 = expf(l1 - m), e2 = expf(l2 - m), e3 = expf(l3 - m);
    const float inv = 1.0f / (e0 + e1 + e2 + e3);
    const float w[NP] = {e0 * inv, e1 * inv, e2 * inv, e3 * inv};

    const float rx = ref[(size_t)bq * 2 + 0];
    const float ry = ref[(size_t)bq * 2 + 1];

    const float* ofp = off + ((size_t)bq * NH + h) * (NP * 2);
    const float* vbase = value + (size_t)b * LIN * CC + h * HD + sub * 8;

    float4 acc0 = make_float4(0.f, 0.f, 0.f, 0.f);
    float4 acc1 = make_float4(0.f, 0.f, 0.f, 0.f);

#pragma unroll
    for (int p = 0; p < NP; p++) {
        const float ox = ofp[p * 2 + 0];
        const float oy = ofp[p * 2 + 1];
        const float x = fmaf(rx, (float)WIMG, ox) - 0.5f;
        const float y = fmaf(ry, (float)HIMG, oy) - 0.5f;
        const float xf = floorf(x), yf = floorf(y);
        const float lx = x - xf, ly = y - yf;
        const int x0 = (int)xf, y0 = (int)yf;
        const float wp = w[p];

        const float cw[4] = {
            (1.0f - lx) * (1.0f - ly) * wp,
            lx * (1.0f - ly) * wp,
            (1.0f - lx) * ly * wp,
            lx * ly * wp
        };
        const int cx[4] = {x0, x0 + 1, x0, x0 + 1};
        const int cy[4] = {y0, y0, y0 + 1, y0 + 1};

#pragma unroll
        for (int c = 0; c < 4; c++) {
            if (cx[c] >= 0 && cx[c] < WIMG && cy[c] >= 0 && cy[c] < HIMG) {
                const float4* vp = reinterpret_cast<const float4*>(
                    vbase + (size_t)(cy[c] * WIMG + cx[c]) * CC);
                const float4 v0 = __ldg(vp);
                const float4 v1 = __ldg(vp + 1);
                const float wc = cw[c];
                acc0.x = fmaf(wc, v0.x, acc0.x); acc0.y = fmaf(wc, v0.y, acc0.y);
                acc0.z = fmaf(wc, v0.z, acc0.z); acc0.w = fmaf(wc, v0.w, acc0.w);
                acc1.x = fmaf(wc, v1.x, acc1.x); acc1.y = fmaf(wc, v1.y, acc1.y);
                acc1.z = fmaf(wc, v1.z, acc1.z); acc1.w = fmaf(wc, v1.w, acc1.w);
            }
        }
    }

    float4* op = reinterpret_cast<float4*>(attn + (size_t)bq * CC + h * HD + sub * 8);
    op[0] = acc0;
    op[1] = acc1;
}

// ---------------------------------------------------------------------------
// out[row] = LayerNorm(x[row] + res[row]) * g + be (warp per row, float4)
// ---------------------------------------------------------------------------
__global__ void __launch_bounds__(256)
add_ln_kernel(const float* __restrict__ x,
              const float* __restrict__ res,
              const float* __restrict__ g,
              const float* __restrict__ be,
              float* __restrict__ out)
{
    const int row  = (blockIdx.x * blockDim.x + threadIdx.x) >> 5;
    const int lane = threadIdx.x & 31;
    if (row >= NROWS) return;

    const float* xr = x   + (size_t)row * CC + lane * 8;
    const float* rr = res + (size_t)row * CC + lane * 8;

    float4 a0 = *reinterpret_cast<const float4*>(xr);
    float4 a1 = *reinterpret_cast<const float4*>(xr + 4);
    const float4 r0 = *reinterpret_cast<const float4*>(rr);
    const float4 r1 = *reinterpret_cast<const float4*>(rr + 4);
    a0.x += r0.x; a0.y += r0.y; a0.z += r0.z; a0.w += r0.w;
    a1.x += r1.x; a1.y += r1.y; a1.z += r1.z; a1.w += r1.w;

    float s = a0.x + a0.y + a0.z + a0.w + a1.x + a1.y + a1.z + a1.w;
#pragma unroll
    for (int o = 16; o > 0; o >>= 1) s += __shfl_xor_sync(0xFFFFFFFFu, s, o);
    const float mean = s * (1.0f / CC);

    float vs = 0.0f;
    vs += (a0.x - mean) * (a0.x - mean); vs += (a0.y - mean) * (a0.y - mean);
    vs += (a0.z - mean) * (a0.z - mean); vs += (a0.w - mean) * (a0.w - mean);
    vs += (a1.x - mean) * (a1.x - mean); vs += (a1.y - mean) * (a1.y - mean);
    vs += (a1.z - mean) * (a1.z - mean); vs += (a1.w - mean) * (a1.w - mean);
#pragma unroll
    for (int o = 16; o > 0; o >>= 1) vs += __shfl_xor_sync(0xFFFFFFFFu, vs, o);
    const float rstd = rsqrtf(vs * (1.0f / CC) + 1e-5f);

    const float4 g0 = *reinterpret_cast<const float4*>(g  + lane * 8);
    const float4 g1 = *reinterpret_cast<const float4*>(g  + lane * 8 + 4);
    const float4 b0 = *reinterpret_cast<const float4*>(be + lane * 8);
    const float4 b1 = *reinterpret_cast<const float4*>(be + lane * 8 + 4);

    float4 o0, o1;
    o0.x = (a0.x - mean) * rstd * g0.x + b0.x;
    o0.y = (a0.y - mean) * rstd * g0.y + b0.y;
    o0.z = (a0.z - mean) * rstd * g0.z + b0.z;
    o0.w = (a0.w - mean) * rstd * g0.w + b0.w;
    o1.x = (a1.x - mean) * rstd * g1.x + b1.x;
    o1.y = (a1.y - mean) * rstd * g1.y + b1.y;
    o1.z = (a1.z - mean) * rstd * g1.z + b1.z;
    o1.w = (a1.w - mean) * rstd * g1.w + b1.w;

    float* orow = out + (size_t)row * CC + lane * 8;
    *reinterpret_cast<float4*>(orow)     = o0;
    *reinterpret_cast<float4*>(orow + 4) = o1;
}

// ---------------------------------------------------------------------------
// Launch
// ---------------------------------------------------------------------------
extern "C" void kernel_launch(void* const* d_in, const int* in_sizes, int n_in,
                              void* d_out, int out_size)
{
    const float* query = (const float*)d_in[0];
    const float* src   = (const float*)d_in[1];
    const float* ref   = (const float*)d_in[2];
    const float* W_off = (const float*)d_in[5];
    const float* b_off = (const float*)d_in[6];
    const float* W_aw  = (const float*)d_in[7];
    const float* b_aw  = (const float*)d_in[8];
    const float* W_val = (const float*)d_in[9];
    const float* b_val = (const float*)d_in[10];
    const float* W_out = (const float*)d_in[11];
    const float* b_out = (const float*)d_in[12];
    const float* g1    = (const float*)d_in[13];
    const float* be1   = (const float*)d_in[14];
    const float* W1    = (const float*)d_in[15];
    const float* b1    = (const float*)d_in[16];
    const float* W2    = (const float*)d_in[17];
    const float* b2    = (const float*)d_in[18];
    const float* g2    = (const float*)d_in[19];
    const float* be2   = (const float*)d_in[20];
    float* out = (float*)d_out;

    float *p_value, *p_off, *p_awl, *p_attn, *p_attnout, *p_q, *p_hidden, *p_ffnout;
    cudaGetSymbolAddress((void**)&p_value,   g_value);
    cudaGetSymbolAddress((void**)&p_off,     g_off);
    cudaGetSymbolAddress((void**)&p_awl,     g_awl);
    cudaGetSymbolAddress((void**)&p_attn,    g_attn);
    cudaGetSymbolAddress((void**)&p_attnout, g_attnout);
    cudaGetSymbolAddress((void**)&p_q,       g_q);
    cudaGetSymbolAddress((void**)&p_hidden,  g_hidden);
    cudaGetSymbolAddress((void**)&p_ffnout,  g_ffnout);

    // Idempotent, deterministic, called every invocation (no static guards).
    cudaFuncSetAttribute(tf32_gemm_kernel<false>,
                         cudaFuncAttributeMaxDynamicSharedMemorySize,
                         (int)GEMM_SMEM_BYTES);
    cudaFuncSetAttribute(tf32_gemm_kernel<true>,
                         cudaFuncAttributeMaxDynamicSharedMemorySize,
                         (int)GEMM_SMEM_BYTES);

    // 1) value = src @ W_val + b_val     [80000,256]
    {
        dim3 grid(CC / TGN, NROWS / TGM);
        tf32_gemm_kernel<false><<<grid, 256, GEMM_SMEM_BYTES>>>(
            NROWS, CC, CC, src, W_val, b_val, p_value);
    }
    // 2) off = query @ W_off + b_off     [80000,64]
    {
        dim3 grid(1, NROWS / 128);
        sgemm_kernel<128, 64, 8, 8, 4, false><<<grid, 256>>>(
            NROWS, 64, CC, query, W_off, b_off, p_off);
    }
    // 3) aw logits = query @ W_aw + b_aw [80000,32]
    {
        dim3 grid(1, NROWS / 128);
        sgemm_kernel<128, 32, 8, 8, 2, false><<<grid, 256>>>(
            NROWS, 32, CC, query, W_aw, b_aw, p_awl);
    }
    // 4) deformable sampling + aggregation -> attn [80000,256]
    {
        const int warps = BB * LQ;   // warp per (b,q)
        sample_kernel<<<(warps + 7) / 8, 256>>>(p_value, p_off, p_awl, ref, p_attn);
    }
    // 5) attnout = attn @ W_out + b_out
    {
        dim3 grid(CC / TGN, NROWS / TGM);
        tf32_gemm_kernel<false><<<grid, 256, GEMM_SMEM_BYTES>>>(
            NROWS, CC, CC, p_attn, W_out, b_out, p_attnout);
    }
    // 6) q = LN(query + attnout)
    add_ln_kernel<<<NROWS / 8, 256>>>(p_attnout, query, g1, be1, p_q);
    // 7) hidden = relu(q @ W1 + b1)      [80000,1024]
    {
        dim3 grid(DFF / TGN, NROWS / TGM);
        tf32_gemm_kernel<true><<<grid, 256, GEMM_SMEM_BYTES>>>(
            NROWS, DFF, CC, p_q, W1, b1, p_hidden);
    }
    // 8) ffnout = hidden @ W2 + b2       [80000,256]
    {
        dim3 grid(CC / TGN, NROWS / TGM);
        tf32_gemm_kernel<false><<<grid, 256, GEMM_SMEM_BYTES>>>(
            NROWS, CC, DFF, p_hidden, W2, b2, p_ffnout);
    }
    // 9) out = LN(q + ffnout)
    add_ln_kernel<<<NROWS / 8, 256>>>(p_ffnout, p_q, g2, be2, out);
}

// round 7
// speedup vs baseline: 3.2969x; 1.0623x over previous
#include <cuda_runtime.h>
#include <cstdint>
#include <cstddef>

// Problem constants (fixed shapes)
#define BB 8
#define LQ 10000
#define LIN 10000
#define CC 256
#define NH 8
#define NP 4
#define HD 32
#define DFF 1024
#define HIMG 100
#define WIMG 100
#define NROWS (BB * LQ)   // 80000

// ---------------------------------------------------------------------------
// Scratch (device globals; no allocations allowed)
// ---------------------------------------------------------------------------
__device__ float g_value  [NROWS * CC];
__device__ float g_offaw  [NROWS * 128];      // packed: cols 0-63 off, 64-95 awl
__device__ float g_attn   [NROWS * CC];
__device__ float g_attnout[NROWS * CC];
__device__ float g_q      [NROWS * CC];
__device__ float g_hidden [NROWS * DFF];
__device__ float g_ffnout [NROWS * CC];
__device__ float g_wcat   [CC * 128];         // W_off | W_aw | 0
__device__ float g_bcat   [128];

// ---------------------------------------------------------------------------
// Async-copy helpers
// ---------------------------------------------------------------------------
__device__ __forceinline__ void cp_async16(void* smem_dst, const void* gsrc) {
    uint32_t d = (uint32_t)__cvta_generic_to_shared(smem_dst);
    asm volatile("cp.async.cg.shared.global [%0], [%1], 16;\n" :: "r"(d), "l"(gsrc));
}
__device__ __forceinline__ void cp_commit() {
    asm volatile("cp.async.commit_group;\n");
}
template <int N>
__device__ __forceinline__ void cp_wait() {
    asm volatile("cp.async.wait_group %0;\n" :: "n"(N));
}

__device__ __forceinline__ void mma_tf32(float* d, const uint32_t* a, const uint32_t* b) {
    asm volatile(
        "mma.sync.aligned.m16n8k8.row.col.f32.tf32.tf32.f32 "
        "{%0,%1,%2,%3}, {%4,%5,%6,%7}, {%8,%9}, {%0,%1,%2,%3};"
        : "+f"(d[0]), "+f"(d[1]), "+f"(d[2]), "+f"(d[3])
        : "r"(a[0]), "r"(a[1]), "r"(a[2]), "r"(a[3]),
          "r"(b[0]), "r"(b[1]));
}

// ---------------------------------------------------------------------------
// TF32 tensor-core GEMM, 3-stage cp.async pipeline.
// Block tile: 128 x BN x 32. 256 threads, 2x4 warp grid, warp tile 64 x (BN/4).
// BN = 128 or 256. Requires M%128==0, N%BN==0, K%32==0.
// ---------------------------------------------------------------------------
#define TGM 128
#define TGK 32
#define LDA 36                  // A row stride (floats)
#define A_TILE (TGM * LDA)      // 4608 floats
#define STAGES 3

__host__ __device__ constexpr size_t gemm_smem_bytes(int BN) {
    return (size_t)STAGES * (A_TILE + TGK * (BN + 8)) * 4;
}

template <int BN, bool RELU>
__global__ void __launch_bounds__(256)
tf32_gemm_kernel(int M, int N, int K,
                 const float* __restrict__ A,
                 const float* __restrict__ B,
                 const float* __restrict__ bias,
                 float* __restrict__ C)
{
    constexpr int NI   = BN / 32;        // n-fragments per warp (4 or 8)
    constexpr int LDBx = BN + 8;
    constexpr int B_TILE = TGK * LDBx;
    constexpr int TPR  = BN / 4;         // threads per B row (float4 each)
    constexpr int RPP  = 256 / TPR;      // rows per pass (8 or 4)
    constexpr int NB   = TGK / RPP;      // B cp.async ops per thread (4 or 8)

    extern __shared__ float sm[];
    float* AsBase = sm;
    float* BsBase = sm + STAGES * A_TILE;

    const int tid  = threadIdx.x;
    const int lane = tid & 31;
    const int warp = tid >> 5;
    const int g    = lane >> 2;
    const int t4   = lane & 3;

    const int wm0 = (warp >> 2) * 64;
    const int wn0 = (warp & 3) * (BN / 4);

    const int blockM = blockIdx.y * TGM;
    const int blockN = blockIdx.x * BN;

    const float* Ap = A + (size_t)blockM * K;
    const float* Bp = B + blockN;
    const float* biasp = bias + blockN;

    const int ar = tid >> 3;            // 0..31 ; rows ar + 32*i
    const int ac = (tid & 7) * 4;       // k col
    const int br = tid / TPR;           // B row base
    const int bc = (tid % TPR) * 4;     // n col

    float acc[4][NI][4];
#pragma unroll
    for (int i = 0; i < 4; i++)
#pragma unroll
        for (int j = 0; j < NI; j++)
#pragma unroll
            for (int r = 0; r < 4; r++) acc[i][j][r] = 0.0f;

    const int ntiles = K / TGK;

    // prologue: stages 0 and 1
#pragma unroll
    for (int s = 0; s < 2; s++) {
        const int k0 = s * TGK;
        float* as = AsBase + s * A_TILE;
        float* bs = BsBase + s * B_TILE;
#pragma unroll
        for (int i = 0; i < 4; i++)
            cp_async16(&as[(ar + 32 * i) * LDA + ac], &Ap[(size_t)(ar + 32 * i) * K + k0 + ac]);
#pragma unroll
        for (int i = 0; i < NB; i++)
            cp_async16(&bs[(br + RPP * i) * LDBx + bc], &Bp[(size_t)(k0 + br + RPP * i) * N + bc]);
        cp_commit();
    }

    int stage = 0;
    for (int kt = 0; kt < ntiles; kt++) {
        if (kt == ntiles - 1) cp_wait<0>(); else cp_wait<1>();
        __syncthreads();

        if (kt + 2 < ntiles) {
            const int s  = (kt + 2) % STAGES;
            const int k0 = (kt + 2) * TGK;
            float* as = AsBase + s * A_TILE;
            float* bs = BsBase + s * B_TILE;
#pragma unroll
            for (int i = 0; i < 4; i++)
                cp_async16(&as[(ar + 32 * i) * LDA + ac], &Ap[(size_t)(ar + 32 * i) * K + k0 + ac]);
#pragma unroll
            for (int i = 0; i < NB; i++)
                cp_async16(&bs[(br + RPP * i) * LDBx + bc], &Bp[(size_t)(k0 + br + RPP * i) * N + bc]);
            cp_commit();
        }

        const float* as = AsBase + stage * A_TILE;
        const float* bs = BsBase + stage * B_TILE;

#pragma unroll
        for (int kk = 0; kk < TGK; kk += 8) {
            uint32_t afr[4][4];
            uint32_t bfr[NI][2];
#pragma unroll
            for (int mi = 0; mi < 4; mi++) {
                const int m = wm0 + mi * 16;
                afr[mi][0] = __float_as_uint(as[(m + g)     * LDA + kk + t4]);
                afr[mi][1] = __float_as_uint(as[(m + g + 8) * LDA + kk + t4]);
                afr[mi][2] = __float_as_uint(as[(m + g)     * LDA + kk + t4 + 4]);
                afr[mi][3] = __float_as_uint(as[(m + g + 8) * LDA + kk + t4 + 4]);
            }
#pragma unroll
            for (int ni = 0; ni < NI; ni++) {
                const int n = wn0 + ni * 8;
                bfr[ni][0] = __float_as_uint(bs[(kk + t4)     * LDBx + n + g]);
                bfr[ni][1] = __float_as_uint(bs[(kk + t4 + 4) * LDBx + n + g]);
            }
#pragma unroll
            for (int mi = 0; mi < 4; mi++)
#pragma unroll
                for (int ni = 0; ni < NI; ni++)
                    mma_tf32(acc[mi][ni], afr[mi], bfr[ni]);
        }
        stage = (stage + 1 == STAGES) ? 0 : stage + 1;
    }

    // epilogue: c0:(g,2t) c1:(g,2t+1) c2:(g+8,2t) c3:(g+8,2t+1)
#pragma unroll
    for (int mi = 0; mi < 4; mi++) {
#pragma unroll
        for (int ni = 0; ni < NI; ni++) {
            const int row0 = blockM + wm0 + mi * 16 + g;
            const int col  = blockN + wn0 + ni * 8 + 2 * t4;
            const float bx = biasp[wn0 + ni * 8 + 2 * t4];
            const float by = biasp[wn0 + ni * 8 + 2 * t4 + 1];
            float v0 = acc[mi][ni][0] + bx;
            float v1 = acc[mi][ni][1] + by;
            float v2 = acc[mi][ni][2] + bx;
            float v3 = acc[mi][ni][3] + by;
            if (RELU) {
                v0 = fmaxf(v0, 0.0f); v1 = fmaxf(v1, 0.0f);
                v2 = fmaxf(v2, 0.0f); v3 = fmaxf(v3, 0.0f);
            }
            *reinterpret_cast<float2*>(&C[(size_t)row0 * N + col])       = make_float2(v0, v1);
            *reinterpret_cast<float2*>(&C[(size_t)(row0 + 8) * N + col]) = make_float2(v2, v3);
        }
    }
}

// ---------------------------------------------------------------------------
// Pack W_off (C x 64) and W_aw (C x 32) into Wcat (C x 128), biases likewise.
// ---------------------------------------------------------------------------
__global__ void pack_w_kernel(const float* __restrict__ W_off,
                              const float* __restrict__ b_off,
                              const float* __restrict__ W_aw,
                              const float* __restrict__ b_aw,
                              float* __restrict__ Wcat,
                              float* __restrict__ bcat)
{
    const int idx = blockIdx.x * blockDim.x + threadIdx.x;
    if (idx < CC * 128) {
        const int k = idx >> 7;
        const int j = idx & 127;
        float v = 0.0f;
        if (j < 64)       v = W_off[k * 64 + j];
        else if (j < 96)  v = W_aw[k * 32 + (j - 64)];
        Wcat[idx] = v;
    }
    if (idx < 128) {
        float v = 0.0f;
        if (idx < 64)       v = b_off[idx];
        else if (idx < 96)  v = b_aw[idx - 64];
        bcat[idx] = v;
    }
}

// ---------------------------------------------------------------------------
// Deformable sampling + attention aggregation.
// One warp per (b,q); lane = (head h = lane>>2, quarter sub = lane&3).
// offaw row layout: [0:64) offsets (h*8 + p*2 + {x,y}), [64:96) logits (h*4+p)
// ---------------------------------------------------------------------------
__global__ void __launch_bounds__(256)
sample_kernel(const float* __restrict__ value,   // [B,Lin,NH,HD]
              const float* __restrict__ offaw,   // [B*Lq, 128] packed
              const float* __restrict__ ref,     // [B,Lq,1,2]
              float* __restrict__ attn)          // [B,Lq,C]
{
    const int warp = (blockIdx.x * blockDim.x + threadIdx.x) >> 5;
    const int lane = threadIdx.x & 31;
    if (warp >= BB * LQ) return;

    const int bq  = warp;
    const int b   = bq / LQ;
    const int h   = lane >> 2;
    const int sub = lane & 3;

    const float* row = offaw + (size_t)bq * 128;

    // softmax over NP=4 logits for this head
    const float* lg = row + 64 + h * NP;
    const float l0 = lg[0], l1 = lg[1], l2 = lg[2], l3 = lg[3];
    const float m  = fmaxf(fmaxf(l0, l1), fmaxf(l2, l3));
    const float e0 = expf(l0 - m), e1 = expf(l1 - m), e2 = expf(l2 - m), e3 = expf(l3 - m);
    const float inv = 1.0f / (e0 + e1 + e2 + e3);
    const float w[NP] = {e0 * inv, e1 * inv, e2 * inv, e3 * inv};

    const float rx = ref[(size_t)bq * 2 + 0];
    const float ry = ref[(size_t)bq * 2 + 1];

    const float* ofp = row + h * (NP * 2);
    const float* vbase = value + (size_t)b * LIN * CC + h * HD + sub * 8;

    float4 acc0 = make_float4(0.f, 0.f, 0.f, 0.f);
    float4 acc1 = make_float4(0.f, 0.f, 0.f, 0.f);

#pragma unroll
    for (int p = 0; p < NP; p++) {
        const float ox = ofp[p * 2 + 0];
        const float oy = ofp[p * 2 + 1];
        const float x = fmaf(rx, (float)WIMG, ox) - 0.5f;
        const float y = fmaf(ry, (float)HIMG, oy) - 0.5f;
        const float xf = floorf(x), yf = floorf(y);
        const float lx = x - xf, ly = y - yf;
        const int x0 = (int)xf, y0 = (int)yf;
        const float wp = w[p];

        const float cw[4] = {
            (1.0f - lx) * (1.0f - ly) * wp,
            lx * (1.0f - ly) * wp,
            (1.0f - lx) * ly * wp,
            lx * ly * wp
        };
        const int cx[4] = {x0, x0 + 1, x0, x0 + 1};
        const int cy[4] = {y0, y0, y0 + 1, y0 + 1};

#pragma unroll
        for (int c = 0; c < 4; c++) {
            if (cx[c] >= 0 && cx[c] < WIMG && cy[c] >= 0 && cy[c] < HIMG) {
                const float4* vp = reinterpret_cast<const float4*>(
                    vbase + (size_t)(cy[c] * WIMG + cx[c]) * CC);
                const float4 v0 = __ldg(vp);
                const float4 v1 = __ldg(vp + 1);
                const float wc = cw[c];
                acc0.x = fmaf(wc, v0.x, acc0.x); acc0.y = fmaf(wc, v0.y, acc0.y);
                acc0.z = fmaf(wc, v0.z, acc0.z); acc0.w = fmaf(wc, v0.w, acc0.w);
                acc1.x = fmaf(wc, v1.x, acc1.x); acc1.y = fmaf(wc, v1.y, acc1.y);
                acc1.z = fmaf(wc, v1.z, acc1.z); acc1.w = fmaf(wc, v1.w, acc1.w);
            }
        }
    }

    float4* op = reinterpret_cast<float4*>(attn + (size_t)bq * CC + h * HD + sub * 8);
    op[0] = acc0;
    op[1] = acc1;
}

// ---------------------------------------------------------------------------
// out[row] = LayerNorm(x[row] + res[row]) * g + be (warp per row, float4)
// ---------------------------------------------------------------------------
__global__ void __launch_bounds__(256)
add_ln_kernel(const float* __restrict__ x,
              const float* __restrict__ res,
              const float* __restrict__ g,
              const float* __restrict__ be,
              float* __restrict__ out)
{
    const int row  = (blockIdx.x * blockDim.x + threadIdx.x) >> 5;
    const int lane = threadIdx.x & 31;
    if (row >= NROWS) return;

    const float* xr = x   + (size_t)row * CC + lane * 8;
    const float* rr = res + (size_t)row * CC + lane * 8;

    float4 a0 = *reinterpret_cast<const float4*>(xr);
    float4 a1 = *reinterpret_cast<const float4*>(xr + 4);
    const float4 r0 = *reinterpret_cast<const float4*>(rr);
    const float4 r1 = *reinterpret_cast<const float4*>(rr + 4);
    a0.x += r0.x; a0.y += r0.y; a0.z += r0.z; a0.w += r0.w;
    a1.x += r1.x; a1.y += r1.y; a1.z += r1.z; a1.w += r1.w;

    float s = a0.x + a0.y + a0.z + a0.w + a1.x + a1.y + a1.z + a1.w;
#pragma unroll
    for (int o = 16; o > 0; o >>= 1) s += __shfl_xor_sync(0xFFFFFFFFu, s, o);
    const float mean = s * (1.0f / CC);

    float vs = 0.0f;
    vs += (a0.x - mean) * (a0.x - mean); vs += (a0.y - mean) * (a0.y - mean);
    vs += (a0.z - mean) * (a0.z - mean); vs += (a0.w - mean) * (a0.w - mean);
    vs += (a1.x - mean) * (a1.x - mean); vs += (a1.y - mean) * (a1.y - mean);
    vs += (a1.z - mean) * (a1.z - mean); vs += (a1.w - mean) * (a1.w - mean);
#pragma unroll
    for (int o = 16; o > 0; o >>= 1) vs += __shfl_xor_sync(0xFFFFFFFFu, vs, o);
    const float rstd = rsqrtf(vs * (1.0f / CC) + 1e-5f);

    const float4 g0 = *reinterpret_cast<const float4*>(g  + lane * 8);
    const float4 g1 = *reinterpret_cast<const float4*>(g  + lane * 8 + 4);
    const float4 b0 = *reinterpret_cast<const float4*>(be + lane * 8);
    const float4 b1 = *reinterpret_cast<const float4*>(be + lane * 8 + 4);

    float4 o0, o1;
    o0.x = (a0.x - mean) * rstd * g0.x + b0.x;
    o0.y = (a0.y - mean) * rstd * g0.y + b0.y;
    o0.z = (a0.z - mean) * rstd * g0.z + b0.z;
    o0.w = (a0.w - mean) * rstd * g0.w + b0.w;
    o1.x = (a1.x - mean) * rstd * g1.x + b1.x;
    o1.y = (a1.y - mean) * rstd * g1.y + b1.y;
    o1.z = (a1.z - mean) * rstd * g1.z + b1.z;
    o1.w = (a1.w - mean) * rstd * g1.w + b1.w;

    float* orow = out + (size_t)row * CC + lane * 8;
    *reinterpret_cast<float4*>(orow)     = o0;
    *reinterpret_cast<float4*>(orow + 4) = o1;
}

// ---------------------------------------------------------------------------
// Launch
// ---------------------------------------------------------------------------
extern "C" void kernel_launch(void* const* d_in, const int* in_sizes, int n_in,
                              void* d_out, int out_size)
{
    const float* query = (const float*)d_in[0];
    const float* src   = (const float*)d_in[1];
    const float* ref   = (const float*)d_in[2];
    const float* W_off = (const float*)d_in[5];
    const float* b_off = (const float*)d_in[6];
    const float* W_aw  = (const float*)d_in[7];
    const float* b_aw  = (const float*)d_in[8];
    const float* W_val = (const float*)d_in[9];
    const float* b_val = (const float*)d_in[10];
    const float* W_out = (const float*)d_in[11];
    const float* b_out = (const float*)d_in[12];
    const float* g1    = (const float*)d_in[13];
    const float* be1   = (const float*)d_in[14];
    const float* W1    = (const float*)d_in[15];
    const float* b1    = (const float*)d_in[16];
    const float* W2    = (const float*)d_in[17];
    const float* b2    = (const float*)d_in[18];
    const float* g2    = (const float*)d_in[19];
    const float* be2   = (const float*)d_in[20];
    float* out = (float*)d_out;

    float *p_value, *p_offaw, *p_attn, *p_attnout, *p_q, *p_hidden, *p_ffnout;
    float *p_wcat, *p_bcat;
    cudaGetSymbolAddress((void**)&p_value,   g_value);
    cudaGetSymbolAddress((void**)&p_offaw,   g_offaw);
    cudaGetSymbolAddress((void**)&p_attn,    g_attn);
    cudaGetSymbolAddress((void**)&p_attnout, g_attnout);
    cudaGetSymbolAddress((void**)&p_q,       g_q);
    cudaGetSymbolAddress((void**)&p_hidden,  g_hidden);
    cudaGetSymbolAddress((void**)&p_ffnout,  g_ffnout);
    cudaGetSymbolAddress((void**)&p_wcat,    g_wcat);
    cudaGetSymbolAddress((void**)&p_bcat,    g_bcat);

    const size_t SM128 = gemm_smem_bytes(128);
    const size_t SM256 = gemm_smem_bytes(256);

    // Idempotent, deterministic; no static guards.
    cudaFuncSetAttribute(tf32_gemm_kernel<128, false>,
                         cudaFuncAttributeMaxDynamicSharedMemorySize, (int)SM128);
    cudaFuncSetAttribute(tf32_gemm_kernel<256, false>,
                         cudaFuncAttributeMaxDynamicSharedMemorySize, (int)SM256);
    cudaFuncSetAttribute(tf32_gemm_kernel<256, true>,
                         cudaFuncAttributeMaxDynamicSharedMemorySize, (int)SM256);

    // 0) pack W_off|W_aw
    pack_w_kernel<<<(CC * 128 + 255) / 256, 256>>>(W_off, b_off, W_aw, b_aw, p_wcat, p_bcat);

    // 1) value = src @ W_val + b_val     [80000,256]
    {
        dim3 grid(CC / 256, NROWS / TGM);
        tf32_gemm_kernel<256, false><<<grid, 256, SM256>>>(
            NROWS, CC, CC, src, W_val, b_val, p_value);
    }
    // 2) offaw = query @ Wcat + bcat     [80000,128]
    {
        dim3 grid(1, NROWS / TGM);
        tf32_gemm_kernel<128, false><<<grid, 256, SM128>>>(
            NROWS, 128, CC, query, p_wcat, p_bcat, p_offaw);
    }
    // 3) deformable sampling + aggregation -> attn [80000,256]
    {
        const int warps = BB * LQ;
        sample_kernel<<<(warps + 7) / 8, 256>>>(p_value, p_offaw, ref, p_attn);
    }
    // 4) attnout = attn @ W_out + b_out
    {
        dim3 grid(CC / 256, NROWS / TGM);
        tf32_gemm_kernel<256, false><<<grid, 256, SM256>>>(
            NROWS, CC, CC, p_attn, W_out, b_out, p_attnout);
    }
    // 5) q = LN(query + attnout)
    add_ln_kernel<<<NROWS / 8, 256>>>(p_attnout, query, g1, be1, p_q);
    // 6) hidden = relu(q @ W1 + b1)      [80000,1024]
    {
        dim3 grid(DFF / 256, NROWS / TGM);
        tf32_gemm_kernel<256, true><<<grid, 256, SM256>>>(
            NROWS, DFF, CC, p_q, W1, b1, p_hidden);
    }
    // 7) ffnout = hidden @ W2 + b2       [80000,256]
    {
        dim3 grid(CC / 256, NROWS / TGM);
        tf32_gemm_kernel<256, false><<<grid, 256, SM256>>>(
            NROWS, CC, DFF, p_hidden, W2, b2, p_ffnout);
    }
    // 8) out = LN(q + ffnout)
    add_ln_kernel<<<NROWS / 8, 256>>>(p_ffnout, p_q, g2, be2, out);
}